// round 4
// baseline (speedup 1.0000x reference)
#include <cuda_runtime.h>
#include <cuda_bf16.h>
#include <math.h>

// ---------------------------------------------------------------------------
// PhotonicDelayReservoirAdaptive — sparse delay-tap reservoir scan, sm_103a.
//
//   fb[b,s]  = sum_k softmax(tapw)[k] * sum_r h[b, t-d_k, r] * W_fb[k,r,s]
//   h_new    = 0.9*h + 0.1*tanh(x[b,t]*W_in[s] + fb[b,s] + bias[s])
//
// R4 design:
//  * 16 clusters x 8 CTAs. Cluster owns 4 batches; rank owns 32 output cols.
//  * Tap-sorted CSR in SMEM: per column, tap-1 entries (idx=r, ~20%) then
//    tap>=4 entries (idx=(k-1)*256+r, ~80%), softmax weight folded in.
//  * Taps d>=4 gathered PRE-barrier from gmem history (visible >=3 phases
//    early); only the tap-1 gather is post-barrier.
//  * Tap-1 row is PUSHED by producers into every CTA's SMEM via
//    mapa + st.shared::cluster (double-buffered by t&1) before arrive;
//    barrier.cluster release/acquire orders it. No post-wait L2 read.
//  * Lane bb<4 of each 8-lane group owns batch bb: parallel tanh, per-lane h.
//  * d>=4 tap loads + x for step t+1 issued during step t's pre-wait segment
//    (latency hidden under the big gather).
// ---------------------------------------------------------------------------

#define T_LEN      2048
#define R_DIM      256
#define N_TAPS     5
#define RANKS      8
#define COLS_PER   32
#define BATCH_PER  4
#define N_CLUSTERS 16
#define CAP        5120
#define NTHREADS   256

// SMEM layout (dynamic):
//   [0,16384)        float4 hist14[1024]   taps {4,24,96,168}, batch-packed
//   [16384,24576)    float  hist0[2][1024] tap-1 double buffer (pushed)
//   [24576,65536)    uint2  csr[CAP]
//   [65536,65668)    int    offA[33]
//   [65668,65796)    int    offB[32]
#define SMEM_H14   0
#define SMEM_H0    16384
#define SMEM_CSR   24576
#define SMEM_OFFA  65536
#define SMEM_OFFB  (65536 + 33*4)
#define SMEM_BYTES 66048

__device__ uint2 g_entries[RANKS * CAP];
__device__ int   g_offA[RANKS * 33];
__device__ int   g_offB[RANKS * 32];

__device__ __forceinline__ unsigned smem_u32(const void* p) {
    unsigned a;
    asm("{ .reg .u64 t; cvta.to.shared.u64 t, %1; cvt.u32.u64 %0, t; }"
        : "=r"(a) : "l"(p));
    return a;
}
__device__ __forceinline__ unsigned ctarank() {
    unsigned r; asm("mov.u32 %0, %%cluster_ctarank;" : "=r"(r)); return r;
}

// ---------------------------------------------------------------------------
// Builder: 1 CTA, thread = output column s. Two-segment CSR (tap-1 first,
// then taps 2..5), each segment padded to a multiple of 8.
// ---------------------------------------------------------------------------
__global__ void build_csr_kernel(const float* __restrict__ W_fb,
                                 const float* __restrict__ tap_weights) {
    __shared__ float tw[N_TAPS];
    __shared__ int p0[R_DIM], p1[R_DIM], cstart[R_DIM], cmid[R_DIM];

    const int s = threadIdx.x;

    if (s == 0) {
        float m = tap_weights[0];
        #pragma unroll
        for (int k = 1; k < N_TAPS; k++) m = fmaxf(m, tap_weights[k]);
        float e[N_TAPS]; float sum = 0.f;
        #pragma unroll
        for (int k = 0; k < N_TAPS; k++) { e[k] = expf(tap_weights[k] - m); sum += e[k]; }
        #pragma unroll
        for (int k = 0; k < N_TAPS; k++) tw[k] = e[k] / sum;
    }

    int c0 = 0, c1 = 0;
    for (int r = 0; r < R_DIM; r++)
        c0 += (W_fb[r * R_DIM + s] != 0.f) ? 1 : 0;
    for (int k = 1; k < N_TAPS; k++)
        for (int r = 0; r < R_DIM; r++)
            c1 += (W_fb[(k * R_DIM + r) * R_DIM + s] != 0.f) ? 1 : 0;
    p0[s] = (c0 + 7) & ~7;
    p1[s] = (c1 + 7) & ~7;
    __syncthreads();

    if (s < RANKS) {
        int off = 0;
        for (int c = 0; c < COLS_PER; c++) {
            int col = s * COLS_PER + c;
            cstart[col] = off;
            g_offA[s * 33 + c] = off;
            cmid[col] = off + p0[col];
            g_offB[s * 32 + c] = off + p0[col];
            off += p0[col] + p1[col];
        }
        g_offA[s * 33 + 32] = off;
    }
    __syncthreads();

    const int rank = s >> 5;
    const int base = rank * CAP;
    int p = cstart[s];
    const int mid  = cmid[s];
    const int pend = mid + p1[s];
    if (pend <= CAP) {
        // tap-1 segment (idx = r)
        for (int r = 0; r < R_DIM; r++) {
            float v = W_fb[r * R_DIM + s];
            if (v != 0.f)
                g_entries[base + p++] = make_uint2(__float_as_uint(v * tw[0]), (unsigned)r);
        }
        for (; p < mid; p++) g_entries[base + p] = make_uint2(0u, 0u);
        // taps 2..5 (idx = (k-1)*256 + r)
        for (int k = 1; k < N_TAPS; k++) {
            const float twk = tw[k];
            for (int r = 0; r < R_DIM; r++) {
                float v = W_fb[(k * R_DIM + r) * R_DIM + s];
                if (v != 0.f)
                    g_entries[base + p++] =
                        make_uint2(__float_as_uint(v * twk), (unsigned)((k - 1) * R_DIM + r));
            }
        }
        for (; p < pend; p++) g_entries[base + p] = make_uint2(0u, 0u);
    }
}

// ---------------------------------------------------------------------------
// Main sequential-scan kernel.
// ---------------------------------------------------------------------------
__global__ void __cluster_dims__(RANKS, 1, 1) __launch_bounds__(NTHREADS, 1)
reservoir_kernel(const float* __restrict__ x,
                 const float* __restrict__ W_in,
                 const float* __restrict__ bias,
                 float* __restrict__ out) {
    extern __shared__ char smem_raw[];
    float4* hist14 = (float4*)(smem_raw + SMEM_H14);   // [1024]
    float*  hist0  = (float*) (smem_raw + SMEM_H0);    // [2][1024]
    uint2*  csr    = (uint2*) (smem_raw + SMEM_CSR);   // [CAP]
    int*    offA   = (int*)   (smem_raw + SMEM_OFFA);  // [33]
    int*    offB   = (int*)   (smem_raw + SMEM_OFFB);  // [32]

    const int tid  = threadIdx.x;
    const unsigned rank = ctarank();
    const unsigned cid  = blockIdx.x >> 3;
    const int b0 = (int)cid * BATCH_PER;

    // ---- prologue ----
    if (tid < 33) offA[tid] = g_offA[rank * 33 + tid];
    if (tid < 32) offB[tid] = g_offB[rank * 32 + tid];
    for (int i = tid; i < CAP; i += NTHREADS)
        csr[i] = g_entries[rank * CAP + i];
    for (int i = tid; i < 2048; i += NTHREADS)
        hist0[i] = 0.f;

    const int colg  = tid >> 3;
    const int lane8 = tid & 7;
    const int s     = (int)rank * COLS_PER + colg;
    const float w_in_s = W_in[s];
    const float bias_s = bias[s];

    const size_t bstride = (size_t)T_LEN * R_DIM;

    float h = 0.f;                       // per-lane state (lane8<4: batch lane8)
    float xcur = 0.f;
    float ecur[4][BATCH_PER];            // taps {4,24,96,168} for current step
    #pragma unroll
    for (int k = 0; k < 4; k++)
        #pragma unroll
        for (int bb = 0; bb < BATCH_PER; bb++) ecur[k][bb] = 0.f;

    unsigned pa[RANKS];                  // remote push addresses (buf 0 word)
    if (lane8 < BATCH_PER) {
        xcur = __ldg(x + (size_t)(b0 + lane8) * T_LEN);
        unsigned la = smem_u32(&hist0[s * 4 + lane8]);
        #pragma unroll
        for (int p = 0; p < RANKS; p++) {
            unsigned ra;
            asm("mapa.shared::cluster.u32 %0, %1, %2;" : "=r"(ra) : "r"(la), "r"(p));
            pa[p] = ra;
        }
    }

    const int myA = (tid < NTHREADS) ? 0 : 0; // (keep compiler happy)
    __syncthreads();
    const int segA = offA[colg];          // tap-1 segment start
    const int segB = offB[colg];          // taps>=4 segment start
    const int segE = offA[colg + 1];      // end
    (void)myA;

    asm volatile("barrier.cluster.arrive.aligned;" ::: "memory");

    for (int t = 0; t < T_LEN; t++) {
        const int buf = t & 1;

        // stage taps {4,24,96,168} (loaded during previous iteration)
        #pragma unroll
        for (int k = 0; k < 4; k++)
            hist14[k * R_DIM + tid] =
                make_float4(ecur[k][0], ecur[k][1], ecur[k][2], ecur[k][3]);

        // prefetch next step's d>=4 taps + x (latency hides under gather)
        float en[4][BATCH_PER];
        float xn = 0.f;
        {
            const int tn = t + 1;
            const int rows[4] = { tn - 4, tn - 24, tn - 96, tn - 168 };
            #pragma unroll
            for (int k = 0; k < 4; k++) {
                const int rk = rows[k];
                if (rk >= 0 && tn < T_LEN) {
                    const float* base = out + (size_t)rk * R_DIM + tid;
                    #pragma unroll
                    for (int bb = 0; bb < BATCH_PER; bb++)
                        en[k][bb] = __ldcg(base + (size_t)(b0 + bb) * bstride);
                } else {
                    #pragma unroll
                    for (int bb = 0; bb < BATCH_PER; bb++) en[k][bb] = 0.f;
                }
            }
            if (lane8 < BATCH_PER && tn < T_LEN)
                xn = __ldg(x + (size_t)(b0 + lane8) * T_LEN + tn);
        }

        __syncthreads();   // hist14 staged

        // big gather: taps >= 4 (pre-barrier, ~80% of nnz)
        float4 acc = make_float4(0.f, 0.f, 0.f, 0.f);
        for (int j = segB + lane8; j < segE; j += 8) {
            const uint2 en2 = csr[j];
            const float v = __uint_as_float(en2.x);
            const float4 hv = hist14[en2.y];
            acc.x = fmaf(v, hv.x, acc.x);
            acc.y = fmaf(v, hv.y, acc.y);
            acc.z = fmaf(v, hv.z, acc.z);
            acc.w = fmaf(v, hv.w, acc.w);
        }

        // tap-1 row becomes visible (pushed into local SMEM by producers)
        asm volatile("barrier.cluster.wait.aligned;" ::: "memory");

        const float4* h0 = (const float4*)(hist0 + buf * 1024);
        for (int j = segA + lane8; j < segB; j += 8) {
            const uint2 en2 = csr[j];
            const float v = __uint_as_float(en2.x);
            const float4 hv = h0[en2.y];
            acc.x = fmaf(v, hv.x, acc.x);
            acc.y = fmaf(v, hv.y, acc.y);
            acc.z = fmaf(v, hv.z, acc.z);
            acc.w = fmaf(v, hv.w, acc.w);
        }

        // reduce across the 8-lane group
        #pragma unroll
        for (int m = 1; m < 8; m <<= 1) {
            acc.x += __shfl_xor_sync(0xffffffffu, acc.x, m);
            acc.y += __shfl_xor_sync(0xffffffffu, acc.y, m);
            acc.z += __shfl_xor_sync(0xffffffffu, acc.z, m);
            acc.w += __shfl_xor_sync(0xffffffffu, acc.w, m);
        }

        // lane bb<4 owns batch bb: parallel tanh, store, cluster push
        if (lane8 < BATCH_PER) {
            const float myacc = (lane8 == 0) ? acc.x :
                                (lane8 == 1) ? acc.y :
                                (lane8 == 2) ? acc.z : acc.w;
            const float hn = 0.9f * h + 0.1f * tanhf(fmaf(xcur, w_in_s, myacc) + bias_s);
            h = hn;
            out[(size_t)(b0 + lane8) * bstride + (size_t)t * R_DIM + s] = hn;

            const unsigned hv = __float_as_uint(hn);
            const unsigned boff = (buf ^ 1) * 4096;   // next buffer, bytes
            #pragma unroll
            for (int p = 0; p < RANKS; p++)
                asm volatile("st.shared::cluster.b32 [%0], %1;"
                             :: "r"(pa[p] + boff), "r"(hv) : "memory");
        }

        // rotate prefetched values
        #pragma unroll
        for (int k = 0; k < 4; k++)
            #pragma unroll
            for (int bb = 0; bb < BATCH_PER; bb++) ecur[k][bb] = en[k][bb];
        xcur = xn;

        // release row t (gmem stores + SMEM pushes) to the cluster
        asm volatile("barrier.cluster.arrive.aligned;" ::: "memory");
    }
    asm volatile("barrier.cluster.wait.aligned;" ::: "memory");
}

// ---------------------------------------------------------------------------
extern "C" void kernel_launch(void* const* d_in, const int* in_sizes, int n_in,
                              void* d_out, int out_size) {
    const float* x           = (const float*)d_in[0];  // (64, 2048, 1)
    const float* W_in        = (const float*)d_in[1];  // (256, 1)
    const float* W_fb        = (const float*)d_in[2];  // (5, 256, 256)
    const float* tap_weights = (const float*)d_in[3];  // (5,)
    const float* bias        = (const float*)d_in[4];  // (256,)
    float* out = (float*)d_out;                        // (64, 2048, 256)

    (void)in_sizes; (void)n_in; (void)out_size;

    cudaFuncSetAttribute(reservoir_kernel,
                         cudaFuncAttributeMaxDynamicSharedMemorySize, SMEM_BYTES);

    build_csr_kernel<<<1, NTHREADS>>>(W_fb, tap_weights);
    reservoir_kernel<<<N_CLUSTERS * RANKS, NTHREADS, SMEM_BYTES>>>(x, W_in, bias, out);
}

// round 5
// speedup vs baseline: 1.1126x; 1.1126x over previous
#include <cuda_runtime.h>
#include <cuda_bf16.h>
#include <math.h>

// ---------------------------------------------------------------------------
// PhotonicDelayReservoirAdaptive — sparse delay-tap reservoir scan, sm_103a.
//
//   fb[b,s]  = sum_k softmax(tapw)[k] * sum_r h[b, t-d_k, r] * W_fb[k,r,s]
//   h_new    = 0.9*h + 0.1*tanh(x[b,t]*W_in[s] + fb[b,s] + bias[s])
//
// R5 design (vs R3/R4):
//  * 16 clusters x 8 CTAs, 512 threads/CTA. Cluster owns 4 batches; rank owns
//    32 output columns (16 lanes per column).
//  * Cross-CTA step sync via per-CTA SMEM mbarrier (count=8):
//    producers: stores -> __syncthreads -> tid<8 remote
//    mbarrier.arrive.release.cluster to all ranks;
//    consumers: mbarrier.try_wait.parity.acquire.cluster on LOCAL barrier
//    (fast path ~90-150 cyc vs barrier.cluster's ~490).
//  * Tap-sorted CSR (tap-1 segment, then taps>=4), segments padded to x32,
//    entries consumed 2-at-a-time via uint4 LDS, dual accumulators.
//  * taps>=4 rows prefetched one step ahead (visible >=2 phases early);
//    gather split 3/4 pre-wait, 1/4 post-wait to cover the tap-1 L2 pull.
//  * Parallel epilogue: lane bb<4 of each 16-lane group owns batch bb.
// ---------------------------------------------------------------------------

#define T_LEN      2048
#define R_DIM      256
#define N_TAPS     5
#define RANKS      8
#define COLS_PER   32
#define BATCH_PER  4
#define CAP        6144
#define NT_MAIN    512
#define NT_BUILD   256

// SMEM layout (dynamic):
//   [0,16384)        float4 hist14[1024]  taps {4,24,96,168}, batch-packed
//   [16384,20480)    float4 hist0[256]    tap-1 row, batch-packed
//   [20480,69632)    uint2  csr[6144]
//   [69632,69764)    int    offA[33]
//   [69764,69892)    int    offB[32]
//   [69896,69904)    u64    mbar
#define SMEM_H14   0
#define SMEM_H0    16384
#define SMEM_CSR   20480
#define SMEM_OFFA  69632
#define SMEM_OFFB  69764
#define SMEM_MBAR  69896
#define SMEM_BYTES 70016

__device__ __align__(16) uint2 g_entries[RANKS * CAP];
__device__ int g_offA[RANKS * 33];
__device__ int g_offB[RANKS * 32];

__device__ __forceinline__ unsigned smem_u32(const void* p) {
    unsigned a;
    asm("{ .reg .u64 t; cvta.to.shared.u64 t, %1; cvt.u32.u64 %0, t; }"
        : "=r"(a) : "l"(p));
    return a;
}
__device__ __forceinline__ unsigned ctarank() {
    unsigned r; asm("mov.u32 %0, %%cluster_ctarank;" : "=r"(r)); return r;
}
__device__ __forceinline__ void mbar_wait_cluster(unsigned addr, unsigned parity) {
    unsigned done;
    asm volatile(
        "{\n\t.reg .pred p;\n\t"
        "mbarrier.try_wait.parity.acquire.cluster.shared::cta.b64 p, [%1], %2;\n\t"
        "selp.b32 %0, 1, 0, p;\n\t}"
        : "=r"(done) : "r"(addr), "r"(parity) : "memory");
    while (!done) {
        asm volatile(
            "{\n\t.reg .pred p;\n\t"
            "mbarrier.try_wait.parity.acquire.cluster.shared::cta.b64 p, [%1], %2, 0x989680;\n\t"
            "selp.b32 %0, 1, 0, p;\n\t}"
            : "=r"(done) : "r"(addr), "r"(parity) : "memory");
    }
}

// ---------------------------------------------------------------------------
// Builder: 1 CTA, thread = output column s. Two-segment CSR (tap-1 entries
// first with idx=r, then taps 2..5 with idx=(k-1)*256+r), softmax tap weight
// folded into values, each segment padded with zero-entries to a multiple
// of 32 (16 lanes x 2-entry vectorized consumption).
// ---------------------------------------------------------------------------
__global__ void build_csr_kernel(const float* __restrict__ W_fb,
                                 const float* __restrict__ tap_weights) {
    __shared__ float tw[N_TAPS];
    __shared__ int p0s[R_DIM], p1s[R_DIM], cstart[R_DIM], cmid[R_DIM];

    const int s = threadIdx.x;

    if (s == 0) {
        float m = tap_weights[0];
        #pragma unroll
        for (int k = 1; k < N_TAPS; k++) m = fmaxf(m, tap_weights[k]);
        float e[N_TAPS]; float sum = 0.f;
        #pragma unroll
        for (int k = 0; k < N_TAPS; k++) { e[k] = expf(tap_weights[k] - m); sum += e[k]; }
        #pragma unroll
        for (int k = 0; k < N_TAPS; k++) tw[k] = e[k] / sum;
    }

    int c0 = 0, c1 = 0;
    for (int r = 0; r < R_DIM; r++)
        c0 += (W_fb[r * R_DIM + s] != 0.f) ? 1 : 0;
    for (int k = 1; k < N_TAPS; k++)
        for (int r = 0; r < R_DIM; r++)
            c1 += (W_fb[(k * R_DIM + r) * R_DIM + s] != 0.f) ? 1 : 0;
    p0s[s] = (c0 + 31) & ~31;
    p1s[s] = (c1 + 31) & ~31;
    __syncthreads();

    if (s < RANKS) {
        int off = 0;
        for (int c = 0; c < COLS_PER; c++) {
            int col = s * COLS_PER + c;
            cstart[col] = off;
            g_offA[s * 33 + c] = off;
            cmid[col] = off + p0s[col];
            g_offB[s * 32 + c] = off + p0s[col];
            off += p0s[col] + p1s[col];
        }
        g_offA[s * 33 + 32] = off;
    }
    __syncthreads();

    const int rank = s >> 5;
    const int base = rank * CAP;
    int p = cstart[s];
    const int mid  = cmid[s];
    const int pend = mid + p1s[s];
    if (pend <= CAP) {
        for (int r = 0; r < R_DIM; r++) {
            float v = W_fb[r * R_DIM + s];
            if (v != 0.f)
                g_entries[base + p++] = make_uint2(__float_as_uint(v * tw[0]), (unsigned)r);
        }
        for (; p < mid; p++) g_entries[base + p] = make_uint2(0u, 0u);
        for (int k = 1; k < N_TAPS; k++) {
            const float twk = tw[k];
            for (int r = 0; r < R_DIM; r++) {
                float v = W_fb[(k * R_DIM + r) * R_DIM + s];
                if (v != 0.f)
                    g_entries[base + p++] =
                        make_uint2(__float_as_uint(v * twk), (unsigned)((k - 1) * R_DIM + r));
            }
        }
        for (; p < pend; p++) g_entries[base + p] = make_uint2(0u, 0u);
    }
}

// ---------------------------------------------------------------------------
// Main sequential-scan kernel.
// ---------------------------------------------------------------------------
__global__ void __cluster_dims__(RANKS, 1, 1) __launch_bounds__(NT_MAIN, 1)
reservoir_kernel(const float* __restrict__ x,
                 const float* __restrict__ W_in,
                 const float* __restrict__ bias,
                 float* __restrict__ out) {
    extern __shared__ char smem_raw[];
    float4* hist14 = (float4*)(smem_raw + SMEM_H14);   // [1024]
    float4* hist0  = (float4*)(smem_raw + SMEM_H0);    // [256]
    uint2*  csr    = (uint2*) (smem_raw + SMEM_CSR);   // [CAP]
    int*    offA   = (int*)   (smem_raw + SMEM_OFFA);  // [33]
    int*    offB   = (int*)   (smem_raw + SMEM_OFFB);  // [32]
    unsigned long long* mbar = (unsigned long long*)(smem_raw + SMEM_MBAR);

    const int tid = threadIdx.x;
    const unsigned rank = ctarank();
    const int b0 = (int)(blockIdx.x >> 3) * BATCH_PER;

    // ---- prologue ----
    if (tid < 33) offA[tid] = g_offA[rank * 33 + tid];
    if (tid < 32) offB[tid] = g_offB[rank * 32 + tid];
    {
        const uint4* src = (const uint4*)(g_entries + rank * CAP);
        uint4* dst = (uint4*)csr;
        for (int i = tid; i < CAP / 2; i += NT_MAIN) dst[i] = src[i];
    }
    for (int i = tid; i < 1024; i += NT_MAIN) hist14[i] = make_float4(0.f, 0.f, 0.f, 0.f);
    if (tid < 256) hist0[tid] = make_float4(0.f, 0.f, 0.f, 0.f);
    const unsigned mbar_local = smem_u32(mbar);
    if (tid == 0) {
        unsigned cnt = RANKS;
        asm volatile("mbarrier.init.shared.b64 [%0], %1;"
                     :: "r"(mbar_local), "r"(cnt) : "memory");
    }
    __syncthreads();
    // all barriers initialized before any remote arrive
    asm volatile("barrier.cluster.arrive.aligned;" ::: "memory");
    asm volatile("barrier.cluster.wait.aligned;"   ::: "memory");

    unsigned mbar_peer = 0;
    if (tid < RANKS) {
        asm("mapa.shared::cluster.u32 %0, %1, %2;"
            : "=r"(mbar_peer) : "r"(mbar_local), "r"(tid));
        // pre-loop arrive: "publishes" the all-zero row -1 (completion #1)
        asm volatile("mbarrier.arrive.release.cluster.shared::cluster.b64 _, [%0];"
                     :: "r"(mbar_peer) : "memory");
    }

    const int r      = tid & 255;          // reservoir row handled for loads
    const int half   = tid >> 8;           // 0: batches {0,1}, 1: batches {2,3}
    const int colg   = tid >> 4;           // output column within slice
    const int lane16 = tid & 15;           // 16-way nnz split
    const int s      = (int)rank * COLS_PER + colg;
    const float w_in_s = W_in[s];
    const float bias_s = bias[s];
    const size_t bstride = (size_t)T_LEN * R_DIM;
    const float* hb0 = out + (size_t)(b0 + half * 2)     * bstride + r;
    const float* hb1 = out + (size_t)(b0 + half * 2 + 1) * bstride + r;

    const int segA = offA[colg];
    const int segB = offB[colg];
    const int segE = offA[colg + 1];
    const int segM = segB + ((((segE - segB) * 3) / 4) & ~31);

    float h = 0.f;                          // lane16<4: state of batch lane16
    float xcur = (lane16 < BATCH_PER) ? __ldg(x + (size_t)(b0 + lane16) * T_LEN) : 0.f;

    for (int t = 0; t < T_LEN; t++) {
        // 1. prefetch taps>=4 rows + x for step t+1 (rows <= t-3: already
        //    covered by the acquire at iteration t-1)
        float en0[4], en1[4];
        float xn = 0.f;
        {
            const int tn = t + 1;
            const int rows[4] = { tn - 4, tn - 24, tn - 96, tn - 168 };
            #pragma unroll
            for (int k = 0; k < 4; k++) {
                if (tn < T_LEN && rows[k] >= 0) {
                    en0[k] = __ldcg(hb0 + (size_t)rows[k] * R_DIM);
                    en1[k] = __ldcg(hb1 + (size_t)rows[k] * R_DIM);
                } else { en0[k] = 0.f; en1[k] = 0.f; }
            }
            if (lane16 < BATCH_PER && tn < T_LEN)
                xn = __ldg(x + (size_t)(b0 + lane16) * T_LEN + tn);
        }

        // 2a. big gather, first 3/4 of taps>=4 segment (pre-wait)
        float4 a0 = make_float4(0.f, 0.f, 0.f, 0.f);
        float4 a1 = make_float4(0.f, 0.f, 0.f, 0.f);
        for (int j = segB + lane16 * 2; j < segM; j += 32) {
            const uint4 e = *(const uint4*)(csr + j);
            const float4 u = hist14[e.y];
            const float4 v = hist14[e.w];
            const float f0 = __uint_as_float(e.x);
            const float f1 = __uint_as_float(e.z);
            a0.x = fmaf(f0, u.x, a0.x); a0.y = fmaf(f0, u.y, a0.y);
            a0.z = fmaf(f0, u.z, a0.z); a0.w = fmaf(f0, u.w, a0.w);
            a1.x = fmaf(f1, v.x, a1.x); a1.y = fmaf(f1, v.y, a1.y);
            a1.z = fmaf(f1, v.z, a1.z); a1.w = fmaf(f1, v.w, a1.w);
        }

        // 3. wait for row t-1 (fast-path try_wait, acquire.cluster)
        mbar_wait_cluster(mbar_local, (unsigned)(t & 1));

        // 4. issue tap-1 loads (latency covered by 2b below)
        float t10 = 0.f, t11 = 0.f;
        if (t > 0) {
            t10 = __ldcg(hb0 + (size_t)(t - 1) * R_DIM);
            t11 = __ldcg(hb1 + (size_t)(t - 1) * R_DIM);
        }

        // 2b. remaining 1/4 of the big gather
        for (int j = segM + lane16 * 2; j < segE; j += 32) {
            const uint4 e = *(const uint4*)(csr + j);
            const float4 u = hist14[e.y];
            const float4 v = hist14[e.w];
            const float f0 = __uint_as_float(e.x);
            const float f1 = __uint_as_float(e.z);
            a0.x = fmaf(f0, u.x, a0.x); a0.y = fmaf(f0, u.y, a0.y);
            a0.z = fmaf(f0, u.z, a0.z); a0.w = fmaf(f0, u.w, a0.w);
            a1.x = fmaf(f1, v.x, a1.x); a1.y = fmaf(f1, v.y, a1.y);
            a1.z = fmaf(f1, v.z, a1.z); a1.w = fmaf(f1, v.w, a1.w);
        }

        // 5. stage tap-1 row (each half writes its 2 batches)
        ((float2*)(hist0 + r))[half] = make_float2(t10, t11);
        __syncthreads();

        // 6. tap-1 gather
        for (int j = segA + lane16 * 2; j < segB; j += 32) {
            const uint4 e = *(const uint4*)(csr + j);
            const float4 u = hist0[e.y];
            const float4 v = hist0[e.w];
            const float f0 = __uint_as_float(e.x);
            const float f1 = __uint_as_float(e.z);
            a0.x = fmaf(f0, u.x, a0.x); a0.y = fmaf(f0, u.y, a0.y);
            a0.z = fmaf(f0, u.z, a0.z); a0.w = fmaf(f0, u.w, a0.w);
            a1.x = fmaf(f1, v.x, a1.x); a1.y = fmaf(f1, v.y, a1.y);
            a1.z = fmaf(f1, v.z, a1.z); a1.w = fmaf(f1, v.w, a1.w);
        }

        float4 acc;
        acc.x = a0.x + a1.x; acc.y = a0.y + a1.y;
        acc.z = a0.z + a1.z; acc.w = a0.w + a1.w;

        // 7. reduce across the 16-lane group
        #pragma unroll
        for (int m = 1; m < 16; m <<= 1) {
            acc.x += __shfl_xor_sync(0xffffffffu, acc.x, m);
            acc.y += __shfl_xor_sync(0xffffffffu, acc.y, m);
            acc.z += __shfl_xor_sync(0xffffffffu, acc.z, m);
            acc.w += __shfl_xor_sync(0xffffffffu, acc.w, m);
        }

        // 8. parallel epilogue: lane bb<4 owns batch bb
        if (lane16 < BATCH_PER) {
            const float myacc = (lane16 == 0) ? acc.x :
                                (lane16 == 1) ? acc.y :
                                (lane16 == 2) ? acc.z : acc.w;
            h = 0.9f * h + 0.1f * tanhf(fmaf(xcur, w_in_s, myacc) + bias_s);
            out[(size_t)(b0 + lane16) * bstride + (size_t)t * R_DIM + s] = h;
        }
        xcur = xn;

        // 9. stage hist14 for step t+1 from the prefetched registers
        #pragma unroll
        for (int k = 0; k < 4; k++)
            ((float2*)(hist14 + k * R_DIM + r))[half] = make_float2(en0[k], en1[k]);
        __syncthreads();   // stores + staging complete CTA-wide

        // 10. publish row t: remote release-arrives to all 8 ranks
        if (tid < RANKS)
            asm volatile("mbarrier.arrive.release.cluster.shared::cluster.b64 _, [%0];"
                         :: "r"(mbar_peer) : "memory");
    }

    // keep SMEM (mbarrier) alive until every CTA is done arriving
    asm volatile("barrier.cluster.arrive.aligned;" ::: "memory");
    asm volatile("barrier.cluster.wait.aligned;"   ::: "memory");
}

// ---------------------------------------------------------------------------
extern "C" void kernel_launch(void* const* d_in, const int* in_sizes, int n_in,
                              void* d_out, int out_size) {
    const float* x           = (const float*)d_in[0];  // (64, 2048, 1)
    const float* W_in        = (const float*)d_in[1];  // (256, 1)
    const float* W_fb        = (const float*)d_in[2];  // (5, 256, 256)
    const float* tap_weights = (const float*)d_in[3];  // (5,)
    const float* bias        = (const float*)d_in[4];  // (256,)
    float* out = (float*)d_out;                        // (64, 2048, 256)

    (void)in_sizes; (void)n_in; (void)out_size;

    cudaFuncSetAttribute(reservoir_kernel,
                         cudaFuncAttributeMaxDynamicSharedMemorySize, SMEM_BYTES);

    build_csr_kernel<<<1, NT_BUILD>>>(W_fb, tap_weights);
    reservoir_kernel<<<16 * RANKS, NT_MAIN, SMEM_BYTES>>>(x, W_in, bias, out);
}